// round 10
// baseline (speedup 1.0000x reference)
#include <cuda_runtime.h>
#include <math.h>

// Problem constants (B=1, C_IN=3, H=W=96, FEAT=64, GDIM=8, BLOCK=16)
#define Hh   96
#define Ww   96
#define HW   (96 * 96)
#define GD   8
#define FEAT 64
#define CIN  3

#define NBX  12            // 12x12 tiles
#define NB   (NBX * NBX)   // 144 blocks
#define NT   512
#define PT   8             // 8x8 pixel tile
#define GT   14            // gaussian halo tile (PT + 6)
#define NG   (GT * GT)     // 196 gaussians per block
#define IT   16            // input patch (GT + 2, conv halo)

#define LN255 5.5412635f   // ln(255); alpha >= 1/255  <=>  sigma <= ln(255)

// 32-byte gaussian record (tile-bounds test proven redundant: radius >= 2
// always, and any sigma-gate survivor has |d| <= 1.665 < radius).
struct __align__(16) GParam {
    float cx, cy, ca, cb, cc, r0, r1, r2;
};

// ---------------------------------------------------------------------------
// Single self-contained kernel per 8x8 pixel tile. Each block redundantly
// computes its 14x14 gaussian halo from a 16x16x3 input patch — everything
// lives in shared memory; no inter-block communication, no grid barrier.
// ---------------------------------------------------------------------------
__global__ __launch_bounds__(NT)
void fused_tile_kernel(const float* __restrict__ inp,
                       const float* __restrict__ w_enc,
                       const float* __restrict__ b_enc,
                       const float* __restrict__ w_head,
                       const float* __restrict__ b_head,
                       float* __restrict__ out)
{
    __shared__ float  s_we[FEAT * 27];     // w_enc [c*27 + k]
    __shared__ float  s_wh[FEAT * GD];     // w_head transposed [c*8 + o]
    __shared__ float  s_be[FEAT];
    __shared__ float  s_bh[GD];
    __shared__ float  sw[GD * 27];         // collapsed weights
    __shared__ float  sb[GD];
    __shared__ float  s_inp[CIN][IT][IT];  // zero-padded input patch
    __shared__ float  spred[NG * 9];       // raw preds, stride 9 (bank-friendly)
    __shared__ GParam s_g[NG];             // gaussian params for the halo

    const int tid = threadIdx.x;
    const int r0 = (blockIdx.x / NBX) * PT;   // tile origin (pixel row)
    const int c0 = (blockIdx.x % NBX) * PT;   // tile origin (pixel col)

    // ---- stage weights + input patch (one cold-memory trip) ----------------
    for (int t = tid; t < FEAT * 27; t += NT) s_we[t] = __ldg(&w_enc[t]);
    {   // transpose w_head into [c][o]  (tid < 512 == FEAT*GD)
        const int c = tid >> 3, o = tid & 7;
        s_wh[c * GD + o] = __ldg(&w_head[o * FEAT + c]);
    }
    if (tid < FEAT) s_be[tid] = __ldg(&b_enc[tid]);
    if (tid < GD)   s_bh[tid] = __ldg(&b_head[tid]);

    // input patch: global rows r0-3..r0+12, cols c0-3..c0+12, zero outside
    for (int t = tid; t < CIN * IT * IT; t += NT) {
        const int ci = t / (IT * IT);
        const int rr = (t / IT) % IT;
        const int cc = t % IT;
        const int y = r0 - 3 + rr;
        const int x = c0 - 3 + cc;
        float v = 0.f;
        if ((unsigned)y < Hh && (unsigned)x < Ww)
            v = __ldg(&inp[ci * HW + y * Ww + x]);
        s_inp[ci][rr][cc] = v;
    }
    __syncthreads();

    // ---- collapse conv+head: w_eff[o,k] = sum_c w_head[o,c] w_enc[c,k] -----
    if (tid < GD * 27) {
        const int o = tid / 27, k = tid % 27;
        float a0 = 0.f, a1 = 0.f, a2 = 0.f, a3 = 0.f;
        #pragma unroll
        for (int c = 0; c < FEAT; c += 4) {
            a0 += s_wh[(c    ) * GD + o] * s_we[(c    ) * 27 + k];
            a1 += s_wh[(c + 1) * GD + o] * s_we[(c + 1) * 27 + k];
            a2 += s_wh[(c + 2) * GD + o] * s_we[(c + 2) * 27 + k];
            a3 += s_wh[(c + 3) * GD + o] * s_we[(c + 3) * 27 + k];
        }
        sw[tid] = (a0 + a1) + (a2 + a3);
    } else if (tid < GD * 27 + GD) {
        const int o = tid - GD * 27;
        float a0 = s_bh[o], a1 = 0.f, a2 = 0.f, a3 = 0.f;
        #pragma unroll
        for (int c = 0; c < FEAT; c += 4) {
            a0 += s_wh[(c    ) * GD + o] * s_be[c    ];
            a1 += s_wh[(c + 1) * GD + o] * s_be[c + 1];
            a2 += s_wh[(c + 2) * GD + o] * s_be[c + 2];
            a3 += s_wh[(c + 3) * GD + o] * s_be[c + 3];
        }
        sb[o] = (a0 + a1) + (a2 + a3);
    }
    __syncthreads();

    // ---- conv over the 14x14 halo: 2 threads per gaussian, 4 channels each -
    if (tid < NG * 2) {
        const int g    = tid >> 1;
        const int half = tid & 1;          // channels half*4 .. half*4+3
        const int lr = g / GT, lc = g % GT;

        float a[4];
        #pragma unroll
        for (int i = 0; i < 4; ++i) a[i] = sb[half * 4 + i];

        #pragma unroll
        for (int ci = 0; ci < CIN; ++ci) {
            #pragma unroll
            for (int ky = 0; ky < 3; ++ky) {
                #pragma unroll
                for (int kx = 0; kx < 3; ++kx) {
                    const float v = s_inp[ci][lr + ky][lc + kx];
                    const int k = ci * 9 + ky * 3 + kx;
                    #pragma unroll
                    for (int i = 0; i < 4; ++i)
                        a[i] += v * sw[(half * 4 + i) * 27 + k];
                }
            }
        }
        #pragma unroll
        for (int i = 0; i < 4; ++i) spred[g * 9 + half * 4 + i] = a[i];
    }
    __syncthreads();

    // ---- activation/covariance: 1 thread per halo gaussian -----------------
    // Halo gaussians outside the image get garbage (zero-padded conv) but are
    // never read: raster checks global bounds before indexing s_g.
    if (tid < NG) {
        const int lr = tid / GT, lc = tid % GT;
        const int h = r0 - 2 + lr;   // global gaussian row
        const int w = c0 - 2 + lc;   // global gaussian col

        float pred[GD];
        #pragma unroll
        for (int o = 0; o < GD; ++o) pred[o] = spred[tid * 9 + o];

        const float theta = (1.f / (1.f + __expf(-pred[3]))) * 6.283185307179586f;
        const float s0 = (1.f / (1.f + __expf(-pred[4]))) * 0.5f + 1e-6f;
        const float s1 = (1.f / (1.f + __expf(-pred[5]))) * 0.5f + 1e-6f;
        const float off0 = tanhf(pred[6]);
        const float off1 = tanhf(pred[7]);

        const float c = __cosf(theta), s = __sinf(theta);
        const float v0 = s0 * s0, v1 = s1 * s1;
        const float S00 = c * c * v0 + s * s * v1;
        const float S01 = c * s * (v0 - v1);
        const float S11 = s * s * v0 + c * c * v1;
        const float det = S00 * S11 - S01 * S01;
        const float inv_det = 1.f / det;

        const float coord0 = 2.0f * (float)w / (float)Ww - 1.0f;
        const float coord1 = 2.0f * (float)h / (float)Hh - 1.0f;
        const float x_ndc = coord0 + 2.0f * off0 / (float)Ww - 1.0f / (float)Ww;
        const float y_ndc = coord1 + 2.0f * off1 / (float)Hh - 1.0f / (float)Hh;

        GParam g;
        g.cx = 0.5f * (float)Ww * (x_ndc + 1.0f) - 0.5f;
        g.cy = 0.5f * (float)Hh * (y_ndc + 1.0f) - 0.5f;
        g.ca =  S11 * inv_det;
        g.cb = -S01 * inv_det;
        g.cc =  S00 * inv_det;
        g.r0 = pred[0]; g.r1 = pred[1]; g.r2 = pred[2];
        s_g[tid] = g;
    }
    __syncthreads();

    // ---- raster: 64 pixels x 8 lanes, candidates from SHARED ---------------
    {
        const int pi  = tid >> 3;          // pixel within tile [0,64)
        const int sub = tid & 7;
        const int pr = pi >> 3, pc = pi & 7;
        const int py = r0 + pr, px = c0 + pc;
        const float fpx = (float)px;
        const float fpy = (float)py;

        float a0 = 0.f, a1 = 0.f, a2 = 0.f;

        #pragma unroll
        for (int j = sub; j < 49; j += 8) {
            const int dh = j / 7, dw = j % 7;
            const int gh = py - 2 + dh;
            const int gw = px - 2 + dw;
            if ((unsigned)gh >= Hh || (unsigned)gw >= Ww) continue;
            const GParam g = s_g[(pr + dh) * GT + (pc + dw)];
            const float dx = g.cx - fpx;
            const float dy = g.cy - fpy;
            const float sigma = 0.5f * (g.ca * dx * dx + g.cc * dy * dy) + g.cb * dx * dy;
            if (!(sigma >= 0.f) || sigma > LN255) continue;
            const float alpha = fminf(0.999f, __expf(-sigma));
            a0 += alpha * g.r0;
            a1 += alpha * g.r1;
            a2 += alpha * g.r2;
        }

        #pragma unroll
        for (int m = 1; m < 8; m <<= 1) {
            a0 += __shfl_xor_sync(0xFFFFFFFFu, a0, m);
            a1 += __shfl_xor_sync(0xFFFFFFFFu, a1, m);
            a2 += __shfl_xor_sync(0xFFFFFFFFu, a2, m);
        }

        const int p = py * Ww + px;
        if (sub == 0)      out[0 * HW + p] = fminf(fmaxf(a0, 0.f), 1.f);
        else if (sub == 1) out[1 * HW + p] = fminf(fmaxf(a1, 0.f), 1.f);
        else if (sub == 2) out[2 * HW + p] = fminf(fmaxf(a2, 0.f), 1.f);
    }
}

// ---------------------------------------------------------------------------
extern "C" void kernel_launch(void* const* d_in, const int* in_sizes, int n_in,
                              void* d_out, int out_size)
{
    const float* inp    = (const float*)d_in[0];
    const float* w_enc  = (const float*)d_in[1];
    const float* b_enc  = (const float*)d_in[2];
    const float* w_head = (const float*)d_in[3];
    const float* b_head = (const float*)d_in[4];
    float* out = (float*)d_out;

    fused_tile_kernel<<<NB, NT>>>(inp, w_enc, b_enc, w_head, b_head, out);
}